// round 16
// baseline (speedup 1.0000x reference)
#include <cuda_runtime.h>
#include <cuda_bf16.h>
#include <cuda_fp16.h>
#include <math.h>
#include <stdint.h>

#define NB 2
#define NH 12
#define HD 64
#define SEQ 2048
#define CDIM 768
#define LSMAX 4.605170185988092f
#define NEPS 1e-12f

// ---------------- scratch ---------------------------------------------------
__device__ __half g_xh [(size_t)NB*SEQ*CDIM];
__device__ __half g_wh [(size_t)3*CDIM*CDIM];
__device__ __half g_owh[(size_t)CDIM*CDIM];
__device__ __half g_qh [(size_t)NB*NH*SEQ*HD];
__device__ __half g_kh [(size_t)NB*NH*SEQ*HD];
__device__ __half g_vh [(size_t)NB*NH*SEQ*HD];
__device__ __half g_aoh[(size_t)NB*SEQ*CDIM];

// ---------------- helpers ---------------------------------------------------
__device__ __forceinline__ uint32_t smem_u32(const void* p) {
    uint32_t a;
    asm("{ .reg .u64 t; cvta.to.shared.u64 t, %1; cvt.u32.u64 %0, t; }" : "=r"(a) : "l"(p));
    return a;
}
__device__ __forceinline__ void ldsm4(uint32_t r[4], uint32_t a) {
    asm volatile("ldmatrix.sync.aligned.m8n8.x4.shared.b16 {%0,%1,%2,%3}, [%4];"
                 : "=r"(r[0]), "=r"(r[1]), "=r"(r[2]), "=r"(r[3]) : "r"(a));
}
__device__ __forceinline__ void ldsm4t(uint32_t r[4], uint32_t a) {
    asm volatile("ldmatrix.sync.aligned.m8n8.x4.trans.shared.b16 {%0,%1,%2,%3}, [%4];"
                 : "=r"(r[0]), "=r"(r[1]), "=r"(r[2]), "=r"(r[3]) : "r"(a));
}
__device__ __forceinline__ void mma_f16(float d[4], const uint32_t a[4], const uint32_t b[2]) {
    asm volatile("mma.sync.aligned.m16n8k16.row.col.f32.f16.f16.f32 "
                 "{%0,%1,%2,%3}, {%4,%5,%6,%7}, {%8,%9}, {%0,%1,%2,%3};"
                 : "+f"(d[0]), "+f"(d[1]), "+f"(d[2]), "+f"(d[3])
                 : "r"(a[0]), "r"(a[1]), "r"(a[2]), "r"(a[3]), "r"(b[0]), "r"(b[1]));
}
__device__ __forceinline__ uint32_t packh2(float a, float b) {
    __half2 h = __floats2half2_rn(a, b);
    return *(uint32_t*)&h;
}
__device__ __forceinline__ void cpa16(uint32_t dst, const void* src) {
    asm volatile("cp.async.cg.shared.global [%0], [%1], 16;" :: "r"(dst), "l"(src));
}
#define CP_COMMIT() asm volatile("cp.async.commit_group;" ::: "memory")
#define CP_WAIT1()  asm volatile("cp.async.wait_group 1;" ::: "memory")
#define CP_WAIT0()  asm volatile("cp.async.wait_group 0;" ::: "memory")

// ---------------- prep: fp32 -> fp16 ----------------------------------------
// Targets referenced from DEVICE code only (R5/R6 lesson: __device__ symbols
// as host args = host shadow addr, silently ATS-writable on GB300).
template<int DST>
__global__ void half_prep(const float* __restrict__ src, int n4)
{
    __half* dst = (DST == 0) ? g_xh : (DST == 1) ? g_wh : g_owh;
    int i = blockIdx.x * blockDim.x + threadIdx.x;
    if (i < n4) {
        float4 v = ((const float4*)src)[i];
        uint2 o;
        o.x = packh2(v.x, v.y);
        o.y = packh2(v.z, v.w);
        ((uint2*)dst)[i] = o;
    }
}

// ---------------- GEMM (qkv / oproj): fp16, 2-stage cp.async ----------------
#define SROW 72
#define G_A(s) ((s)*36864 + 0)
#define G_B(s) ((s)*36864 + 18432)
#define G_BIAS  73728
#define GEMM_SMEM (73728 + 512)
#define CPAD 133

__device__ __forceinline__ void g_load_stage(uint32_t smb, int s,
        const __half* A, const __half* B, int c, int tid)
{
    #pragma unroll
    for (int i = 0; i < 4; i++) {
        int p = tid + i * 256;               // 0..1023
        int row = p >> 3, ch = p & 7;
        size_t go = (size_t)row * CDIM + c * 64 + ch * 8;
        uint32_t so = (uint32_t)(row * SROW + ch * 8) * 2;
        cpa16(smb + G_A(s) + so, A + go);
        cpa16(smb + G_B(s) + so, B + go);
    }
}

// CTA 128x128, K=768 in 12 chunks of 64, 8 warps (2x4), warp tile 64x32.
__device__ __forceinline__ void gemm_cp(char* sm, uint32_t smb,
        const __half* A, const __half* B, float d[4][4][4], int tid)
{
    const int wid = tid >> 5, lane = tid & 31;
    const int wm = (wid >> 2) * 64, wn = (wid & 3) * 32;
    const int arow = lane & 15, acol8 = (lane >> 4) << 3;
    const int brow = (lane & 7) | ((lane >> 1) & 8);
    const int bcol8 = lane & 8;

    g_load_stage(smb, 0, A, B, 0, tid);
    CP_COMMIT();

    for (int c = 0; c < 12; c++) {
        const int s = c & 1;
        if (c < 11) {
            g_load_stage(smb, s ^ 1, A, B, c + 1, tid);
            CP_COMMIT();
            CP_WAIT1();
        } else {
            CP_WAIT0();
        }
        __syncthreads();

        #pragma unroll
        for (int ks = 0; ks < 4; ks++) {
            int k0 = ks * 16;
            uint32_t af[4][4];
            #pragma unroll
            for (int mt = 0; mt < 4; mt++) {
                uint32_t off = ((wm + mt * 16 + arow) * SROW + k0 + acol8) * 2;
                ldsm4(af[mt], smb + G_A(s) + off);
            }
            uint32_t bf[2][4];
            #pragma unroll
            for (int g = 0; g < 2; g++) {
                uint32_t off = ((wn + g * 16 + brow) * SROW + k0 + bcol8) * 2;
                ldsm4(bf[g], smb + G_B(s) + off);
            }
            #pragma unroll
            for (int mt = 0; mt < 4; mt++)
                #pragma unroll
                for (int nt = 0; nt < 4; nt++)
                    mma_f16(d[mt][nt], af[mt], &bf[nt >> 1][(nt & 1) * 2]);
        }
        __syncthreads();
    }

    float* sC = (float*)sm;
    const int g = lane >> 2, tg = lane & 3;
    #pragma unroll
    for (int mt = 0; mt < 4; mt++)
        #pragma unroll
        for (int nt = 0; nt < 4; nt++) {
            int r = wm + mt * 16 + g, cc = wn + nt * 8 + tg * 2;
            sC[r * CPAD + cc]           = d[mt][nt][0];
            sC[r * CPAD + cc + 1]       = d[mt][nt][1];
            sC[(r + 8) * CPAD + cc]     = d[mt][nt][2];
            sC[(r + 8) * CPAD + cc + 1] = d[mt][nt][3];
        }
    __syncthreads();
}

// ---------------------------------------------------------------------------
// Kernel 1: QKV projection. grid (18, 32), block 256, 2 CTAs/SM.
// ---------------------------------------------------------------------------
__global__ __launch_bounds__(256, 2)
void qkv_tc(const float* __restrict__ bias, const float* __restrict__ logit_scale)
{
    extern __shared__ __align__(16) char sm[];
    uint32_t smb = smem_u32(sm);
    const int tid = threadIdx.x;
    const int bx = blockIdx.x, by = blockIdx.y;
    const int comp = bx / 6;
    const int h0 = (bx % 6) * 2;
    const int f0 = bx * 128;
    const int m0 = by * 128;

    if (tid < 128) ((float*)(sm + G_BIAS))[tid] = bias[f0 + tid];

    float d[4][4][4] = {};
    gemm_cp(sm, smb, g_xh + (size_t)m0 * CDIM, g_wh + (size_t)f0 * CDIM, d, tid);

    const float* sC = (const float*)sm;
    const float* sB = (const float*)(sm + G_BIAS);
    const int row = tid & 127, half = tid >> 7;
    const int h = h0 + half;

    float vals[64];
    float ss = 0.f;
    #pragma unroll
    for (int j = 0; j < 64; j++) {
        float v = sC[row * CPAD + half * 64 + j] + sB[half * 64 + j];
        vals[j] = v; ss += v * v;
    }
    const int m = m0 + row;
    const int n = m >> 11, l = m & (SEQ - 1);
    const size_t ob = (((size_t)n * NH + h) * SEQ + l) * HD;

    float scl = 1.0f;
    __half* dst = g_vh;
    if (comp < 2) {
        scl = 1.0f / fmaxf(sqrtf(ss), NEPS);
        if (comp == 0) scl *= __expf(fminf(logit_scale[h], LSMAX));
        dst = (comp == 0) ? g_qh : g_kh;
    }
    #pragma unroll
    for (int j4 = 0; j4 < 16; j4++) {
        uint2 o;
        o.x = packh2(vals[j4*4+0]*scl, vals[j4*4+1]*scl);
        o.y = packh2(vals[j4*4+2]*scl, vals[j4*4+3]*scl);
        *(uint2*)(dst + ob + j4 * 4) = o;
    }
}

// ---------------------------------------------------------------------------
// Kernel 3: out projection. grid (6, 32), block 256, 2 CTAs/SM.
// ---------------------------------------------------------------------------
__global__ __launch_bounds__(256, 2)
void oproj_tc(const float* __restrict__ bias, float* __restrict__ out)
{
    extern __shared__ __align__(16) char sm[];
    uint32_t smb = smem_u32(sm);
    const int tid = threadIdx.x;
    const int f0 = blockIdx.x * 128;
    const int m0 = blockIdx.y * 128;

    if (tid < 128) ((float*)(sm + G_BIAS))[tid] = bias[f0 + tid];

    float d[4][4][4] = {};
    gemm_cp(sm, smb, g_aoh + (size_t)m0 * CDIM, g_owh + (size_t)f0 * CDIM, d, tid);

    const float* sC = (const float*)sm;
    const float* sB = (const float*)(sm + G_BIAS);
    const int row = tid & 127, half = tid >> 7;
    float* ob = out + (size_t)(m0 + row) * CDIM + f0 + half * 64;
    #pragma unroll
    for (int j4 = 0; j4 < 16; j4++) {
        float4 o;
        o.x = sC[row * CPAD + half * 64 + j4*4+0] + sB[half * 64 + j4*4+0];
        o.y = sC[row * CPAD + half * 64 + j4*4+1] + sB[half * 64 + j4*4+1];
        o.z = sC[row * CPAD + half * 64 + j4*4+2] + sB[half * 64 + j4*4+2];
        o.w = sC[row * CPAD + half * 64 + j4*4+3] + sB[half * 64 + j4*4+3];
        *(float4*)(ob + j4 * 4) = o;
    }
}

// ---------------------------------------------------------------------------
// Kernel 2: flash attention, fp16 MMA, BM=128, BN=128 (16 chunks).
// grid (16, 12, 2), block 256, 2-stage cp.async, 2 CTAs/SM.
// ---------------------------------------------------------------------------
#define F_Q   0
#define FKV(s) (18432 + (s)*36864)
#define FK    0
#define FV    18432
#define FLASH_SMEM 92160
#define OPAD 66
#define NCH2 (SEQ / 128)

__device__ __forceinline__ void f_load_stage(uint32_t smb, int s, size_t base,
                                             int kt, int tid)
{
    #pragma unroll
    for (int i = 0; i < 4; i++) {
        int p = tid + i * 256;               // 0..1023
        int row = p >> 3, ch = p & 7;
        size_t go = base + (size_t)(kt * 128 + row) * HD + ch * 8;
        uint32_t so = (uint32_t)(row * SROW + ch * 8) * 2;
        cpa16(smb + FKV(s) + FK + so, g_kh + go);
        cpa16(smb + FKV(s) + FV + so, g_vh + go);
    }
}

__global__ __launch_bounds__(256, 2)
void flash_tc(const float* __restrict__ mask, const float* __restrict__ lscale)
{
    extern __shared__ __align__(16) char sm[];
    uint32_t smb = smem_u32(sm);
    const int tid = threadIdx.x, wid = tid >> 5, lane = tid & 31;
    const int qt = blockIdx.x, h = blockIdx.y, n = blockIdx.z;
    const int q0 = qt * 128;
    const size_t base = (((size_t)n * NH + h) * SEQ) * HD;

    const int arow = lane & 15, acol8 = (lane >> 4) << 3;
    const int brow = (lane & 7) | ((lane >> 1) & 8);
    const int bcol8 = lane & 8;
    const int g_ = lane >> 2, tg = lane & 3;

    // Q (fp16) into smem
    #pragma unroll
    for (int i = 0; i < 8; i++) {
        int p = tid + i * 256;
        int row = p >> 4, c4 = (p & 15) * 4;
        size_t go = base + (size_t)(q0 + row) * HD + c4;
        uint32_t so = (uint32_t)(row * SROW + c4) * 2;
        *(uint2*)(sm + F_Q + so) = *(const uint2*)(g_qh + go);
    }

    f_load_stage(smb, 0, base, 0, tid);
    CP_COMMIT();

    float O[8][4] = {};
    float m0r = -INFINITY, m1r = -INFINITY, l0r = 0.f, l1r = 0.f;

    for (int kt = 0; kt < NCH2; kt++) {
        const int s = kt & 1;
        if (kt < NCH2 - 1) {
            f_load_stage(smb, s ^ 1, base, kt + 1, tid);
            CP_COMMIT();
            CP_WAIT1();
        } else {
            CP_WAIT0();
        }
        __syncthreads();

        // S = Q K^T (fp16), 16 N-frags of 8 cols
        float S[16][4] = {};
        #pragma unroll
        for (int ks = 0; ks < 4; ks++) {
            int k0 = ks * 16;
            uint32_t qf[4];
            uint32_t qoff = ((wid * 16 + arow) * SROW + k0 + acol8) * 2;
            ldsm4(qf, smb + F_Q + qoff);
            #pragma unroll
            for (int g = 0; g < 8; g++) {
                uint32_t kf[4];
                uint32_t off = ((g * 16 + brow) * SROW + k0 + bcol8) * 2;
                ldsm4(kf, smb + FKV(s) + FK + off);
                mma_f16(S[2*g],   qf, &kf[0]);
                mma_f16(S[2*g+1], qf, &kf[2]);
            }
        }

        // additive mask
        const int r0 = q0 + wid * 16 + g_, r1 = r0 + 8;
        #pragma unroll
        for (int nt = 0; nt < 16; nt++) {
            int cc = kt * 128 + nt * 8 + tg * 2;
            float2 a = *(const float2*)(mask + (size_t)r0 * SEQ + cc);
            float2 b = *(const float2*)(mask + (size_t)r1 * SEQ + cc);
            S[nt][0] += a.x; S[nt][1] += a.y; S[nt][2] += b.x; S[nt][3] += b.y;
        }

        // online softmax (rows g_, g_+8; 4 threads/row -> xor 1,2)
        float mx0 = -INFINITY, mx1 = -INFINITY;
        #pragma unroll
        for (int nt = 0; nt < 16; nt++) {
            mx0 = fmaxf(mx0, fmaxf(S[nt][0], S[nt][1]));
            mx1 = fmaxf(mx1, fmaxf(S[nt][2], S[nt][3]));
        }
        mx0 = fmaxf(mx0, __shfl_xor_sync(0xffffffff, mx0, 1));
        mx0 = fmaxf(mx0, __shfl_xor_sync(0xffffffff, mx0, 2));
        mx1 = fmaxf(mx1, __shfl_xor_sync(0xffffffff, mx1, 1));
        mx1 = fmaxf(mx1, __shfl_xor_sync(0xffffffff, mx1, 2));
        float mn0 = fmaxf(m0r, mx0), mn1 = fmaxf(m1r, mx1);
        float al0 = __expf(m0r - mn0), al1 = __expf(m1r - mn1);
        m0r = mn0; m1r = mn1;
        float s0 = 0.f, s1 = 0.f;
        #pragma unroll
        for (int nt = 0; nt < 16; nt++) {
            S[nt][0] = __expf(S[nt][0] - mn0); s0 += S[nt][0];
            S[nt][1] = __expf(S[nt][1] - mn0); s0 += S[nt][1];
            S[nt][2] = __expf(S[nt][2] - mn1); s1 += S[nt][2];
            S[nt][3] = __expf(S[nt][3] - mn1); s1 += S[nt][3];
        }
        s0 += __shfl_xor_sync(0xffffffff, s0, 1);
        s0 += __shfl_xor_sync(0xffffffff, s0, 2);
        s1 += __shfl_xor_sync(0xffffffff, s1, 1);
        s1 += __shfl_xor_sync(0xffffffff, s1, 2);
        l0r = l0r * al0 + s0;
        l1r = l1r * al1 + s1;
        #pragma unroll
        for (int dt = 0; dt < 8; dt++) {
            O[dt][0] *= al0; O[dt][1] *= al0; O[dt][2] *= al1; O[dt][3] *= al1;
        }

        // O += P V: per-ks pack of P (keeps pa live-range at 4 regs)
        #pragma unroll
        for (int ks = 0; ks < 8; ks++) {
            uint32_t pa[4];
            pa[0] = packh2(S[2*ks][0],   S[2*ks][1]);
            pa[1] = packh2(S[2*ks][2],   S[2*ks][3]);
            pa[2] = packh2(S[2*ks+1][0], S[2*ks+1][1]);
            pa[3] = packh2(S[2*ks+1][2], S[2*ks+1][3]);
            #pragma unroll
            for (int g = 0; g < 4; g++) {
                uint32_t vb[4];
                uint32_t off = ((ks * 16 + arow) * SROW + g * 16 + acol8) * 2;
                ldsm4t(vb, smb + FKV(s) + FV + off);
                mma_f16(O[2*g],   pa, &vb[0]);
                mma_f16(O[2*g+1], pa, &vb[2]);
            }
        }
        __syncthreads();
    }

    // epilogue: 1/l * learned_scale, stage via smem, fp16 store to g_aoh
    const float lsc = lscale[h];
    const float inv0 = lsc / l0r, inv1 = lsc / l1r;
    float* sO = (float*)sm;
    #pragma unroll
    for (int dt = 0; dt < 8; dt++) {
        int r = wid * 16 + g_, cc = dt * 8 + tg * 2;
        sO[r * OPAD + cc]           = O[dt][0] * inv0;
        sO[r * OPAD + cc + 1]       = O[dt][1] * inv0;
        sO[(r + 8) * OPAD + cc]     = O[dt][2] * inv1;
        sO[(r + 8) * OPAD + cc + 1] = O[dt][3] * inv1;
    }
    __syncthreads();
    const int row = tid & 127, half = tid >> 7;
    const size_t ob = ((size_t)n * SEQ + q0 + row) * CDIM + h * HD + half * 32;
    #pragma unroll
    for (int j4 = 0; j4 < 8; j4++) {
        uint2 o;
        o.x = packh2(sO[row * OPAD + half * 32 + j4*4+0],
                     sO[row * OPAD + half * 32 + j4*4+1]);
        o.y = packh2(sO[row * OPAD + half * 32 + j4*4+2],
                     sO[row * OPAD + half * 32 + j4*4+3]);
        *(uint2*)(g_aoh + ob + j4 * 4) = o;
    }
}

// ---------------------------------------------------------------------------
extern "C" void kernel_launch(void* const* d_in, const int* in_sizes, int n_in,
                              void* d_out, int out_size)
{
    const float* x   = (const float*)d_in[0];
    const float* ipw = (const float*)d_in[1];
    const float* ipb = (const float*)d_in[2];
    const float* lgs = (const float*)d_in[3];
    const float* lsc = (const float*)d_in[4];
    const float* opw = (const float*)d_in[5];
    const float* opb = (const float*)d_in[6];
    const float* msk = (const float*)d_in[7];
    float* out = (float*)d_out;

    cudaFuncSetAttribute(qkv_tc,   cudaFuncAttributeMaxDynamicSharedMemorySize, GEMM_SMEM);
    cudaFuncSetAttribute(oproj_tc, cudaFuncAttributeMaxDynamicSharedMemorySize, GEMM_SMEM);
    cudaFuncSetAttribute(flash_tc, cudaFuncAttributeMaxDynamicSharedMemorySize, FLASH_SMEM);

    half_prep<0><<<(NB*SEQ*CDIM/4 + 255)/256, 256>>>(x,   NB*SEQ*CDIM/4);
    half_prep<1><<<(3*CDIM*CDIM/4 + 255)/256, 256>>>(ipw, 3*CDIM*CDIM/4);
    half_prep<2><<<(CDIM*CDIM/4   + 255)/256, 256>>>(opw, CDIM*CDIM/4);

    qkv_tc<<<dim3(18, 32), 256, GEMM_SMEM>>>(ipb, lgs);
    flash_tc<<<dim3(SEQ / 128, NH, NB), 256, FLASH_SMEM>>>(msk, lsc);
    oproj_tc<<<dim3(6, 32), 256, GEMM_SMEM>>>(opb, out);
}

// round 17
// speedup vs baseline: 1.3740x; 1.3740x over previous
#include <cuda_runtime.h>
#include <cuda_bf16.h>
#include <cuda_fp16.h>
#include <math.h>
#include <stdint.h>

#define NB 2
#define NH 12
#define HD 64
#define SEQ 2048
#define CDIM 768
#define LSMAX 4.605170185988092f
#define NEPS 1e-12f

// ---------------- scratch ---------------------------------------------------
__device__ __half g_xh [(size_t)NB*SEQ*CDIM];
__device__ __half g_wh [(size_t)3*CDIM*CDIM];
__device__ __half g_owh[(size_t)CDIM*CDIM];
__device__ __half g_qh [(size_t)NB*NH*SEQ*HD];
__device__ __half g_kh [(size_t)NB*NH*SEQ*HD];
__device__ __half g_vh [(size_t)NB*NH*SEQ*HD];
__device__ __half g_aoh[(size_t)NB*SEQ*CDIM];
__device__ int    g_mask_nz;

// ---------------- helpers ---------------------------------------------------
__device__ __forceinline__ uint32_t smem_u32(const void* p) {
    uint32_t a;
    asm("{ .reg .u64 t; cvta.to.shared.u64 t, %1; cvt.u32.u64 %0, t; }" : "=r"(a) : "l"(p));
    return a;
}
__device__ __forceinline__ void ldsm4(uint32_t r[4], uint32_t a) {
    asm volatile("ldmatrix.sync.aligned.m8n8.x4.shared.b16 {%0,%1,%2,%3}, [%4];"
                 : "=r"(r[0]), "=r"(r[1]), "=r"(r[2]), "=r"(r[3]) : "r"(a));
}
__device__ __forceinline__ void ldsm4t(uint32_t r[4], uint32_t a) {
    asm volatile("ldmatrix.sync.aligned.m8n8.x4.trans.shared.b16 {%0,%1,%2,%3}, [%4];"
                 : "=r"(r[0]), "=r"(r[1]), "=r"(r[2]), "=r"(r[3]) : "r"(a));
}
__device__ __forceinline__ void mma_f16(float d[4], const uint32_t a[4], const uint32_t b[2]) {
    asm volatile("mma.sync.aligned.m16n8k16.row.col.f32.f16.f16.f32 "
                 "{%0,%1,%2,%3}, {%4,%5,%6,%7}, {%8,%9}, {%0,%1,%2,%3};"
                 : "+f"(d[0]), "+f"(d[1]), "+f"(d[2]), "+f"(d[3])
                 : "r"(a[0]), "r"(a[1]), "r"(a[2]), "r"(a[3]), "r"(b[0]), "r"(b[1]));
}
__device__ __forceinline__ uint32_t packh2(float a, float b) {
    __half2 h = __floats2half2_rn(a, b);
    return *(uint32_t*)&h;
}
__device__ __forceinline__ void cpa16(uint32_t dst, const void* src) {
    asm volatile("cp.async.cg.shared.global [%0], [%1], 16;" :: "r"(dst), "l"(src));
}
#define CP_COMMIT() asm volatile("cp.async.commit_group;" ::: "memory")
#define CP_WAIT2()  asm volatile("cp.async.wait_group 2;" ::: "memory")
#define CP_WAIT1()  asm volatile("cp.async.wait_group 1;" ::: "memory")
#define CP_WAIT0()  asm volatile("cp.async.wait_group 0;" ::: "memory")

// ---------------- prep: fused fp32->fp16 + mask scan -------------------------
// Targets referenced from DEVICE code only (R5/R6 lesson: __device__ symbols
// as host args = host shadow addr, silently ATS-writable on GB300).
#define N0 (NB*SEQ*CDIM/4)
#define N1 (3*CDIM*CDIM/4)
#define N2 (CDIM*CDIM/4)

__global__ void prep_all(const float* __restrict__ x,
                         const float* __restrict__ w,
                         const float* __restrict__ ow)
{
    int i = blockIdx.x * blockDim.x + threadIdx.x;
    const float4* src;
    __half* dst;
    int j;
    if (i < N0)            { src = (const float4*)x;  dst = g_xh;  j = i; }
    else if (i < N0 + N1)  { src = (const float4*)w;  dst = g_wh;  j = i - N0; }
    else if (i < N0+N1+N2) { src = (const float4*)ow; dst = g_owh; j = i - N0 - N1; }
    else return;
    float4 v = src[j];
    uint2 o;
    o.x = packh2(v.x, v.y);
    o.y = packh2(v.z, v.w);
    ((uint2*)dst)[j] = o;
}

__global__ void mask_reset() { g_mask_nz = 0; }

__global__ void mask_scan(const float* __restrict__ m, int n4)
{
    int i = blockIdx.x * blockDim.x + threadIdx.x;
    int nz = 0;
    if (i < n4) {
        float4 v = ((const float4*)m)[i];
        nz = (v.x != 0.f) | (v.y != 0.f) | (v.z != 0.f) | (v.w != 0.f);
    }
    if (__syncthreads_or(nz)) {
        if (threadIdx.x == 0) atomicOr(&g_mask_nz, 1);
    }
}

// ---------------- GEMM (qkv / oproj): fp16, 2-stage cp.async ----------------
#define SROW 72
#define G_A(s) ((s)*36864 + 0)
#define G_B(s) ((s)*36864 + 18432)
#define G_BIAS  73728
#define GEMM_SMEM (73728 + 512)
#define CPAD 133

__device__ __forceinline__ void g_load_stage(uint32_t smb, int s,
        const __half* A, const __half* B, int c, int tid)
{
    #pragma unroll
    for (int i = 0; i < 4; i++) {
        int p = tid + i * 256;               // 0..1023
        int row = p >> 3, ch = p & 7;
        size_t go = (size_t)row * CDIM + c * 64 + ch * 8;
        uint32_t so = (uint32_t)(row * SROW + ch * 8) * 2;
        cpa16(smb + G_A(s) + so, A + go);
        cpa16(smb + G_B(s) + so, B + go);
    }
}

// CTA 128x128, K=768 in 12 chunks of 64, 8 warps (2x4), warp tile 64x32.
__device__ __forceinline__ void gemm_cp(char* sm, uint32_t smb,
        const __half* A, const __half* B, float d[4][4][4], int tid)
{
    const int wid = tid >> 5, lane = tid & 31;
    const int wm = (wid >> 2) * 64, wn = (wid & 3) * 32;
    const int arow = lane & 15, acol8 = (lane >> 4) << 3;
    const int brow = (lane & 7) | ((lane >> 1) & 8);
    const int bcol8 = lane & 8;

    g_load_stage(smb, 0, A, B, 0, tid);
    CP_COMMIT();

    for (int c = 0; c < 12; c++) {
        const int s = c & 1;
        if (c < 11) {
            g_load_stage(smb, s ^ 1, A, B, c + 1, tid);
            CP_COMMIT();
            CP_WAIT1();
        } else {
            CP_WAIT0();
        }
        __syncthreads();

        #pragma unroll
        for (int ks = 0; ks < 4; ks++) {
            int k0 = ks * 16;
            uint32_t af[4][4];
            #pragma unroll
            for (int mt = 0; mt < 4; mt++) {
                uint32_t off = ((wm + mt * 16 + arow) * SROW + k0 + acol8) * 2;
                ldsm4(af[mt], smb + G_A(s) + off);
            }
            uint32_t bf[2][4];
            #pragma unroll
            for (int g = 0; g < 2; g++) {
                uint32_t off = ((wn + g * 16 + brow) * SROW + k0 + bcol8) * 2;
                ldsm4(bf[g], smb + G_B(s) + off);
            }
            #pragma unroll
            for (int mt = 0; mt < 4; mt++)
                #pragma unroll
                for (int nt = 0; nt < 4; nt++)
                    mma_f16(d[mt][nt], af[mt], &bf[nt >> 1][(nt & 1) * 2]);
        }
        __syncthreads();
    }

    float* sC = (float*)sm;
    const int g = lane >> 2, tg = lane & 3;
    #pragma unroll
    for (int mt = 0; mt < 4; mt++)
        #pragma unroll
        for (int nt = 0; nt < 4; nt++) {
            int r = wm + mt * 16 + g, cc = wn + nt * 8 + tg * 2;
            sC[r * CPAD + cc]           = d[mt][nt][0];
            sC[r * CPAD + cc + 1]       = d[mt][nt][1];
            sC[(r + 8) * CPAD + cc]     = d[mt][nt][2];
            sC[(r + 8) * CPAD + cc + 1] = d[mt][nt][3];
        }
    __syncthreads();
}

// ---------------------------------------------------------------------------
// Kernel 1: QKV projection. grid (18, 32), block 256, 2 CTAs/SM.
// ---------------------------------------------------------------------------
__global__ __launch_bounds__(256, 2)
void qkv_tc(const float* __restrict__ bias, const float* __restrict__ logit_scale)
{
    extern __shared__ __align__(16) char sm[];
    uint32_t smb = smem_u32(sm);
    const int tid = threadIdx.x;
    const int bx = blockIdx.x, by = blockIdx.y;
    const int comp = bx / 6;
    const int h0 = (bx % 6) * 2;
    const int f0 = bx * 128;
    const int m0 = by * 128;

    if (tid < 128) ((float*)(sm + G_BIAS))[tid] = bias[f0 + tid];

    float d[4][4][4] = {};
    gemm_cp(sm, smb, g_xh + (size_t)m0 * CDIM, g_wh + (size_t)f0 * CDIM, d, tid);

    const float* sC = (const float*)sm;
    const float* sB = (const float*)(sm + G_BIAS);
    const int row = tid & 127, half = tid >> 7;
    const int h = h0 + half;

    float vals[64];
    float ss = 0.f;
    #pragma unroll
    for (int j = 0; j < 64; j++) {
        float v = sC[row * CPAD + half * 64 + j] + sB[half * 64 + j];
        vals[j] = v; ss += v * v;
    }
    const int m = m0 + row;
    const int n = m >> 11, l = m & (SEQ - 1);
    const size_t ob = (((size_t)n * NH + h) * SEQ + l) * HD;

    float scl = 1.0f;
    __half* dst = g_vh;
    if (comp < 2) {
        scl = 1.0f / fmaxf(sqrtf(ss), NEPS);
        if (comp == 0) scl *= __expf(fminf(logit_scale[h], LSMAX));
        dst = (comp == 0) ? g_qh : g_kh;
    }
    #pragma unroll
    for (int j4 = 0; j4 < 16; j4++) {
        uint2 o;
        o.x = packh2(vals[j4*4+0]*scl, vals[j4*4+1]*scl);
        o.y = packh2(vals[j4*4+2]*scl, vals[j4*4+3]*scl);
        *(uint2*)(dst + ob + j4 * 4) = o;
    }
}

// ---------------------------------------------------------------------------
// Kernel 3: out projection. grid (6, 32), block 256, 2 CTAs/SM.
// ---------------------------------------------------------------------------
__global__ __launch_bounds__(256, 2)
void oproj_tc(const float* __restrict__ bias, float* __restrict__ out)
{
    extern __shared__ __align__(16) char sm[];
    uint32_t smb = smem_u32(sm);
    const int tid = threadIdx.x;
    const int f0 = blockIdx.x * 128;
    const int m0 = blockIdx.y * 128;

    if (tid < 128) ((float*)(sm + G_BIAS))[tid] = bias[f0 + tid];

    float d[4][4][4] = {};
    gemm_cp(sm, smb, g_aoh + (size_t)m0 * CDIM, g_owh + (size_t)f0 * CDIM, d, tid);

    const float* sC = (const float*)sm;
    const float* sB = (const float*)(sm + G_BIAS);
    const int row = tid & 127, half = tid >> 7;
    float* ob = out + (size_t)(m0 + row) * CDIM + f0 + half * 64;
    #pragma unroll
    for (int j4 = 0; j4 < 16; j4++) {
        float4 o;
        o.x = sC[row * CPAD + half * 64 + j4*4+0] + sB[half * 64 + j4*4+0];
        o.y = sC[row * CPAD + half * 64 + j4*4+1] + sB[half * 64 + j4*4+1];
        o.z = sC[row * CPAD + half * 64 + j4*4+2] + sB[half * 64 + j4*4+2];
        o.w = sC[row * CPAD + half * 64 + j4*4+3] + sB[half * 64 + j4*4+3];
        *(float4*)(ob + j4 * 4) = o;
    }
}

// ---------------------------------------------------------------------------
// Kernel 2: flash attention, fp16 MMA (1-pass QK, 1-pass PV). BM=128, BN=64.
// grid (16, 12, 2), block 256, 3-stage cp.async, 2 CTAs/SM. (R15 config)
// ---------------------------------------------------------------------------
#define F_Q   0
#define FKV(s) (18432 + (s)*18432)
#define FK    0
#define FV    9216
#define FLASH_SMEM 73728
#define OPAD 66
#define NCHUNK (SEQ / 64)

__device__ __forceinline__ void f_load_stage(uint32_t smb, int s, size_t base,
                                             int kt, int tid)
{
    #pragma unroll
    for (int i = 0; i < 2; i++) {
        int p = tid + i * 256;               // 0..511
        int row = p >> 3, ch = p & 7;
        size_t go = base + (size_t)(kt * 64 + row) * HD + ch * 8;
        uint32_t so = (uint32_t)(row * SROW + ch * 8) * 2;
        cpa16(smb + FKV(s) + FK + so, g_kh + go);
        cpa16(smb + FKV(s) + FV + so, g_vh + go);
    }
}

__global__ __launch_bounds__(256, 2)
void flash_tc(const float* __restrict__ mask, const float* __restrict__ lscale)
{
    extern __shared__ __align__(16) char sm[];
    uint32_t smb = smem_u32(sm);
    const int tid = threadIdx.x, wid = tid >> 5, lane = tid & 31;
    const int qt = blockIdx.x, h = blockIdx.y, n = blockIdx.z;
    const int q0 = qt * 128;
    const size_t base = (((size_t)n * NH + h) * SEQ) * HD;
    const int mnz = g_mask_nz;

    const int arow = lane & 15, acol8 = (lane >> 4) << 3;
    const int brow = (lane & 7) | ((lane >> 1) & 8);
    const int bcol8 = lane & 8;
    const int g_ = lane >> 2, tg = lane & 3;

    // Q (fp16) into smem
    #pragma unroll
    for (int i = 0; i < 8; i++) {
        int p = tid + i * 256;
        int row = p >> 4, c4 = (p & 15) * 4;
        size_t go = base + (size_t)(q0 + row) * HD + c4;
        uint32_t so = (uint32_t)(row * SROW + c4) * 2;
        *(uint2*)(sm + F_Q + so) = *(const uint2*)(g_qh + go);
    }

    f_load_stage(smb, 0, base, 0, tid); CP_COMMIT();
    f_load_stage(smb, 1, base, 1, tid); CP_COMMIT();

    float O[8][4] = {};
    float m0r = -INFINITY, m1r = -INFINITY, l0r = 0.f, l1r = 0.f;

    for (int kt = 0; kt < NCHUNK; kt++) {
        const int s = kt % 3;
        if (kt + 2 < NCHUNK) {
            f_load_stage(smb, (kt + 2) % 3, base, kt + 2, tid);
            CP_COMMIT();
            CP_WAIT2();
        } else if (kt + 1 < NCHUNK) {
            CP_WAIT1();
        } else {
            CP_WAIT0();
        }
        __syncthreads();

        // S = Q K^T (single-pass fp16)
        float S[8][4] = {};
        #pragma unroll
        for (int ks = 0; ks < 4; ks++) {
            int k0 = ks * 16;
            uint32_t qf[4];
            uint32_t qoff = ((wid * 16 + arow) * SROW + k0 + acol8) * 2;
            ldsm4(qf, smb + F_Q + qoff);
            uint32_t kf[4][4];
            #pragma unroll
            for (int g = 0; g < 4; g++) {
                uint32_t off = ((g * 16 + brow) * SROW + k0 + bcol8) * 2;
                ldsm4(kf[g], smb + FKV(s) + FK + off);
            }
            #pragma unroll
            for (int nt = 0; nt < 8; nt++)
                mma_f16(S[nt], qf, &kf[nt >> 1][(nt & 1) * 2]);
        }

        // additive mask (skipped uniformly when mask is all-zero)
        if (mnz) {
            const int r0 = q0 + wid * 16 + g_, r1 = r0 + 8;
            #pragma unroll
            for (int nt = 0; nt < 8; nt++) {
                int cc = kt * 64 + nt * 8 + tg * 2;
                float2 a = *(const float2*)(mask + (size_t)r0 * SEQ + cc);
                float2 b = *(const float2*)(mask + (size_t)r1 * SEQ + cc);
                S[nt][0] += a.x; S[nt][1] += a.y; S[nt][2] += b.x; S[nt][3] += b.y;
            }
        }

        // online softmax (rows g_, g_+8; 4 threads/row -> xor 1,2)
        float mx0 = -INFINITY, mx1 = -INFINITY;
        #pragma unroll
        for (int nt = 0; nt < 8; nt++) {
            mx0 = fmaxf(mx0, fmaxf(S[nt][0], S[nt][1]));
            mx1 = fmaxf(mx1, fmaxf(S[nt][2], S[nt][3]));
        }
        mx0 = fmaxf(mx0, __shfl_xor_sync(0xffffffff, mx0, 1));
        mx0 = fmaxf(mx0, __shfl_xor_sync(0xffffffff, mx0, 2));
        mx1 = fmaxf(mx1, __shfl_xor_sync(0xffffffff, mx1, 1));
        mx1 = fmaxf(mx1, __shfl_xor_sync(0xffffffff, mx1, 2));
        float mn0 = fmaxf(m0r, mx0), mn1 = fmaxf(m1r, mx1);
        float al0 = __expf(m0r - mn0), al1 = __expf(m1r - mn1);
        m0r = mn0; m1r = mn1;
        float s0 = 0.f, s1 = 0.f;
        #pragma unroll
        for (int nt = 0; nt < 8; nt++) {
            S[nt][0] = __expf(S[nt][0] - mn0); s0 += S[nt][0];
            S[nt][1] = __expf(S[nt][1] - mn0); s0 += S[nt][1];
            S[nt][2] = __expf(S[nt][2] - mn1); s1 += S[nt][2];
            S[nt][3] = __expf(S[nt][3] - mn1); s1 += S[nt][3];
        }
        s0 += __shfl_xor_sync(0xffffffff, s0, 1);
        s0 += __shfl_xor_sync(0xffffffff, s0, 2);
        s1 += __shfl_xor_sync(0xffffffff, s1, 1);
        s1 += __shfl_xor_sync(0xffffffff, s1, 2);
        l0r = l0r * al0 + s0;
        l1r = l1r * al1 + s1;
        #pragma unroll
        for (int dt = 0; dt < 8; dt++) {
            O[dt][0] *= al0; O[dt][1] *= al0; O[dt][2] *= al1; O[dt][3] *= al1;
        }

        // P -> fp16 A-frags; O += P V (single-pass fp16)
        uint32_t pa[4][4];
        #pragma unroll
        for (int k2 = 0; k2 < 4; k2++) {
            pa[k2][0] = packh2(S[2*k2][0],   S[2*k2][1]);
            pa[k2][1] = packh2(S[2*k2][2],   S[2*k2][3]);
            pa[k2][2] = packh2(S[2*k2+1][0], S[2*k2+1][1]);
            pa[k2][3] = packh2(S[2*k2+1][2], S[2*k2+1][3]);
        }
        #pragma unroll
        for (int ks = 0; ks < 4; ks++) {
            uint32_t vb[4][4];
            #pragma unroll
            for (int g = 0; g < 4; g++) {
                uint32_t off = ((ks * 16 + arow) * SROW + g * 16 + acol8) * 2;
                ldsm4t(vb[g], smb + FKV(s) + FV + off);
            }
            #pragma unroll
            for (int dt = 0; dt < 8; dt++)
                mma_f16(O[dt], pa[ks], &vb[dt >> 1][(dt & 1) * 2]);
        }
        __syncthreads();
    }

    // epilogue: 1/l * learned_scale, stage via smem, fp16 store to g_aoh
    const float lsc = lscale[h];
    const float inv0 = lsc / l0r, inv1 = lsc / l1r;
    float* sO = (float*)sm;
    #pragma unroll
    for (int dt = 0; dt < 8; dt++) {
        int r = wid * 16 + g_, cc = dt * 8 + tg * 2;
        sO[r * OPAD + cc]           = O[dt][0] * inv0;
        sO[r * OPAD + cc + 1]       = O[dt][1] * inv0;
        sO[(r + 8) * OPAD + cc]     = O[dt][2] * inv1;
        sO[(r + 8) * OPAD + cc + 1] = O[dt][3] * inv1;
    }
    __syncthreads();
    const int row = tid & 127, half = tid >> 7;
    const size_t ob = ((size_t)n * SEQ + q0 + row) * CDIM + h * HD + half * 32;
    #pragma unroll
    for (int j4 = 0; j4 < 8; j4++) {
        uint2 o;
        o.x = packh2(sO[row * OPAD + half * 32 + j4*4+0],
                     sO[row * OPAD + half * 32 + j4*4+1]);
        o.y = packh2(sO[row * OPAD + half * 32 + j4*4+2],
                     sO[row * OPAD + half * 32 + j4*4+3]);
        *(uint2*)(g_aoh + ob + j4 * 4) = o;
    }
}

// ---------------------------------------------------------------------------
extern "C" void kernel_launch(void* const* d_in, const int* in_sizes, int n_in,
                              void* d_out, int out_size)
{
    const float* x   = (const float*)d_in[0];
    const float* ipw = (const float*)d_in[1];
    const float* ipb = (const float*)d_in[2];
    const float* lgs = (const float*)d_in[3];
    const float* lsc = (const float*)d_in[4];
    const float* opw = (const float*)d_in[5];
    const float* opb = (const float*)d_in[6];
    const float* msk = (const float*)d_in[7];
    float* out = (float*)d_out;

    cudaFuncSetAttribute(qkv_tc,   cudaFuncAttributeMaxDynamicSharedMemorySize, GEMM_SMEM);
    cudaFuncSetAttribute(oproj_tc, cudaFuncAttributeMaxDynamicSharedMemorySize, GEMM_SMEM);
    cudaFuncSetAttribute(flash_tc, cudaFuncAttributeMaxDynamicSharedMemorySize, FLASH_SMEM);

    mask_reset<<<1, 1>>>();
    mask_scan<<<(SEQ*SEQ/4 + 255)/256, 256>>>(msk, SEQ*SEQ/4);
    prep_all<<<(N0+N1+N2 + 255)/256, 256>>>(x, ipw, opw);

    qkv_tc<<<dim3(18, 32), 256, GEMM_SMEM>>>(ipb, lgs);
    flash_tc<<<dim3(SEQ / 128, NH, NB), 256, FLASH_SMEM>>>(msk, lsc);
    oproj_tc<<<dim3(6, 32), 256, GEMM_SMEM>>>(opb, out);
}